// round 15
// baseline (speedup 1.0000x reference)
#include <cuda_runtime.h>
#include <cuda_bf16.h>
#include <mma.h>
#include <cstdint>

using namespace nvcuda;

typedef unsigned long long u64;
#define DEVINL __device__ __forceinline__

DEVINL u64 pack2(float lo, float hi) {
    u64 d;
    asm("mov.b64 %0, {%1, %2};" : "=l"(d) : "f"(lo), "f"(hi));
    return d;
}
DEVINL void unpack2(u64 v, float& lo, float& hi) {
    asm("mov.b64 {%0, %1}, %2;" : "=f"(lo), "=f"(hi) : "l"(v));
}
DEVINL u64 ffma2(u64 a, u64 b, u64 c) {
    u64 d;
    asm("fma.rn.f32x2 %0, %1, %2, %3;" : "=l"(d) : "l"(a), "l"(b), "l"(c));
    return d;
}

// smooth_leaky_relu(x) = 0.6x + 0.4x*tanh(x/2)   (alpha=0.2)
DEVINL float act_fn(float v) {
    float t;
    asm("tanh.approx.f32 %0, %1;" : "=f"(t) : "f"(0.5f * v));
    return v * (0.6f + 0.4f * t);
}

static constexpr int ROWLEN = 592;

extern __shared__ float smem[];

// ===================== weights scratch =====================
__device__ float g_wt[21760];                 // fp32 [k][o] (only seg3 range used)
__device__ __nv_bfloat16 g_w0hi[16384];       // seg0 W0 bf16 hi/lo, natural [o][k]
__device__ __nv_bfloat16 g_w0lo[16384];
__device__ __nv_bfloat16 g_wshi[5120];        // seg1 [0,4096) + seg2 [4096,5120), natural [o][k]
__device__ __nv_bfloat16 g_wslo[5120];

__global__ void prep_w0(const float* __restrict__ w0) {
    int idx = blockIdx.x * 256 + threadIdx.x;
    if (idx >= 16384) return;
    float w = w0[idx];
    __nv_bfloat16 h = __float2bfloat16(w);
    g_w0hi[idx] = h;
    g_w0lo[idx] = __float2bfloat16(w - __bfloat162float(h));
}

__global__ void prep_ws(const float* __restrict__ w1, const float* __restrict__ w2) {
    int idx = blockIdx.x * 256 + threadIdx.x;
    if (idx >= 5120) return;
    float w = (idx < 4096) ? w1[idx] : w2[idx - 4096];
    __nv_bfloat16 h = __float2bfloat16(w);
    g_wshi[idx] = h;
    g_wslo[idx] = __float2bfloat16(w - __bfloat162float(h));
}

__global__ void prep_w3(const float* __restrict__ w3) {
    int t = threadIdx.x;           // 256 entries: [k][o]
    int k = t >> 4, o = t & 15;
    g_wt[21504 + t] = w3[o * 16 + k];
}

// ===================== seg0: wmma bf16-split GEMM, 64x64 block tile =====================
// Each block: 64 rows x 64 outputs (output dim split across 2 blocks).
static constexpr int LDA0 = 72;     // bf16 pitch
static constexpr int LDO0 = 68;     // f32 pitch
static constexpr int F_BIAS0 = 0;                        // 64 floats
static constexpr int F_AHI0  = 64;                       // 64*72/2 = 2304 floats each
static constexpr int F_ALO0  = F_AHI0 + 2304;
static constexpr int F_WHI0  = F_ALO0 + 2304;            // 64*72/2 = 2304 floats each
static constexpr int F_WLO0  = F_WHI0 + 2304;
static constexpr int SM0_BYTES = (F_WLO0 + 2304) * 4;    // 37120

__global__ __launch_bounds__(256, 4)
void seg0_wmma(const float* __restrict__ x, const float* __restrict__ b0,
               float* __restrict__ out, int N) {
    const int tid = threadIdx.x, warp = tid >> 5;
    const int r0  = (blockIdx.x >> 1) * 64;
    const int ob0 = (blockIdx.x & 1) * 64;

    __nv_bfloat16* sAh = (__nv_bfloat16*)(smem + F_AHI0);
    __nv_bfloat16* sAl = (__nv_bfloat16*)(smem + F_ALO0);
    __nv_bfloat16* sWh = (__nv_bfloat16*)(smem + F_WHI0);
    __nv_bfloat16* sWl = (__nv_bfloat16*)(smem + F_WLO0);

    if (tid < 64) smem[F_BIAS0 + tid] = b0[ob0 + tid];

    const int wrow = (warp >> 1) * 16;   // 0,16,32,48
    const int wcol = (warp & 1) * 32;    // 0,32

    wmma::fragment<wmma::accumulator, 16, 16, 16, float> acc[2];
    wmma::fill_fragment(acc[0], 0.0f);
    wmma::fill_fragment(acc[1], 0.0f);

    #pragma unroll 1
    for (int c = 0; c < 2; c++) {
        __syncthreads();
        // ---- stage A chunk: 64 rows x 64 k, bf16 hi/lo split ----
        #pragma unroll 1
        for (int i = tid; i < 64 * 16; i += 256) {
            int row = i >> 4, q = i & 15;
            float4 v = make_float4(0.f, 0.f, 0.f, 0.f);
            if (r0 + row < N)
                v = *(const float4*)(x + (size_t)(r0 + row) * ROWLEN + 64 * c + 4 * q);
            __nv_bfloat16 h0 = __float2bfloat16(v.x), h1 = __float2bfloat16(v.y);
            __nv_bfloat16 h2 = __float2bfloat16(v.z), h3 = __float2bfloat16(v.w);
            float l0 = v.x - __bfloat162float(h0), l1 = v.y - __bfloat162float(h1);
            float l2 = v.z - __bfloat162float(h2), l3 = v.w - __bfloat162float(h3);
            __nv_bfloat162 hp0 = __halves2bfloat162(h0, h1);
            __nv_bfloat162 hp1 = __halves2bfloat162(h2, h3);
            __nv_bfloat162 lp0 = __floats2bfloat162_rn(l0, l1);
            __nv_bfloat162 lp1 = __floats2bfloat162_rn(l2, l3);
            uint2 uh; uh.x = *(uint32_t*)&hp0; uh.y = *(uint32_t*)&hp1;
            uint2 ul; ul.x = *(uint32_t*)&lp0; ul.y = *(uint32_t*)&lp1;
            *(uint2*)(sAh + row * LDA0 + 4 * q) = uh;
            *(uint2*)(sAl + row * LDA0 + 4 * q) = ul;
        }
        // ---- stage W chunk: 64 o x 64 k (pre-split bf16) ----
        #pragma unroll 1
        for (int i = tid; i < 64 * 8; i += 256) {
            int o = i >> 3, q = i & 7;
            *(uint4*)(sWh + o * LDA0 + 8 * q) =
                *(const uint4*)(g_w0hi + (ob0 + o) * 128 + 64 * c + 8 * q);
            *(uint4*)(sWl + o * LDA0 + 8 * q) =
                *(const uint4*)(g_w0lo + (ob0 + o) * 128 + 64 * c + 8 * q);
        }
        __syncthreads();

        #pragma unroll
        for (int ks = 0; ks < 4; ks++) {
            wmma::fragment<wmma::matrix_b, 16, 16, 16, __nv_bfloat16, wmma::col_major> bh[2], bl[2];
            #pragma unroll
            for (int n = 0; n < 2; n++) {
                wmma::load_matrix_sync(bh[n], sWh + (wcol + 16 * n) * LDA0 + 16 * ks, LDA0);
                wmma::load_matrix_sync(bl[n], sWl + (wcol + 16 * n) * LDA0 + 16 * ks, LDA0);
            }
            wmma::fragment<wmma::matrix_a, 16, 16, 16, __nv_bfloat16, wmma::row_major> ah, al;
            wmma::load_matrix_sync(ah, sAh + wrow * LDA0 + 16 * ks, LDA0);
            wmma::load_matrix_sync(al, sAl + wrow * LDA0 + 16 * ks, LDA0);
            #pragma unroll
            for (int n = 0; n < 2; n++) {
                wmma::mma_sync(acc[n], ah, bh[n], acc[n]);
                wmma::mma_sync(acc[n], ah, bl[n], acc[n]);
                wmma::mma_sync(acc[n], al, bh[n], acc[n]);
            }
        }
    }
    __syncthreads();

    // Os: 64*68 = 4352 floats, fits in staging area
    float* Os = smem + F_AHI0;
    #pragma unroll
    for (int n = 0; n < 2; n++)
        wmma::store_matrix_sync(Os + wrow * LDO0 + wcol + 16 * n,
                                acc[n], LDO0, wmma::mem_row_major);
    __syncthreads();

    const float* bias_s = smem + F_BIAS0;
    #pragma unroll 1
    for (int i = tid; i < 64 * 16; i += 256) {
        int row = i >> 4, q = i & 15;
        if (r0 + row < N) {
            const float* src = Os + row * LDO0 + 4 * q;
            float4 v;
            v.x = act_fn(src[0] + bias_s[4 * q + 0]);
            v.y = act_fn(src[1] + bias_s[4 * q + 1]);
            v.z = act_fn(src[2] + bias_s[4 * q + 2]);
            v.w = act_fn(src[3] + bias_s[4 * q + 3]);
            *(float4*)(out + (size_t)(r0 + row) * ROWLEN + ob0 + 4 * q) = v;
        }
    }
}

// ===================== generic interleaved wmma kernel (seg1/seg2) =====================
// GEMM rows rho = r*D + d, padded to GPAD (multiple of 16*WGR); pad rows zeroed.
template<int MUL, int D, int R, int GPAD, int WGR, int WGC, int IN_OFF, int WOFF, int MINB>
__global__ __launch_bounds__(256, MINB)
void seg_wmma(const float* __restrict__ x, const float* __restrict__ bias,
              float* __restrict__ out, int N) {
    constexpr int K      = MUL;
    constexpr int GROWS  = R * D;
    constexpr int SEGLEN = MUL * D;
    constexpr int SEGF4  = SEGLEN / 4;
    constexpr int LDW    = K + 8;          // bf16 pitch
    constexpr int LDO    = MUL + 4;        // f32 pitch for Os
    constexpr int RT     = GPAD / 16;
    constexpr int CT     = MUL / 16;
    constexpr int WM     = RT / WGR;
    constexpr int WN     = CT / WGC;
    constexpr int KS     = K / 16;
    constexpr int ASZ    = GPAD * LDW / 2;
    constexpr int WSZ    = MUL * LDW / 2;
    constexpr int F_AH   = MUL;
    constexpr int F_AL   = F_AH + ASZ;
    constexpr int F_WH   = F_AL + ASZ;
    constexpr int F_WL   = F_WH + WSZ;
    static_assert(WGR * WGC == 8, "");
    static_assert(RT % WGR == 0 && CT % WGC == 0, "");
    static_assert(GPAD % 16 == 0 && GPAD >= GROWS, "");

    const int tid = threadIdx.x, warp = tid >> 5;
    const int r0 = blockIdx.x * R;
    const int nrows = min(R, N - r0);

    __nv_bfloat16* sAh = (__nv_bfloat16*)(smem + F_AH);
    __nv_bfloat16* sAl = (__nv_bfloat16*)(smem + F_AL);
    __nv_bfloat16* sWh = (__nv_bfloat16*)(smem + F_WH);
    __nv_bfloat16* sWl = (__nv_bfloat16*)(smem + F_WL);

    if (tid < MUL) smem[tid] = bias[tid];

    // ---- zero pad rows (if any) ----
    if (GPAD > GROWS) {
        constexpr int PADW = (GPAD - GROWS) * LDW / 2;   // uint32 count per copy
        uint32_t* ph = (uint32_t*)(sAh + GROWS * LDW);
        uint32_t* pl = (uint32_t*)(sAl + GROWS * LDW);
        #pragma unroll 1
        for (int i = tid; i < PADW; i += 256) { ph[i] = 0; pl[i] = 0; }
    }

    #pragma unroll 1
    for (int i = tid; i < R * SEGF4; i += 256) {
        int r = i / SEGF4, q = i - r * SEGF4;
        float4 v = make_float4(0.f, 0.f, 0.f, 0.f);
        if (r0 + r < N)
            v = *(const float4*)(x + (size_t)(r0 + r) * ROWLEN + IN_OFF + 4 * q);
        float vv[4] = {v.x, v.y, v.z, v.w};
        int j = 4 * q;
        #pragma unroll
        for (int e = 0; e < 4; e++) {
            int jj = j + e;
            int m  = jj / D;
            int d  = jj - m * D;
            float w = vv[e];
            __nv_bfloat16 h = __float2bfloat16(w);
            sAh[(r * D + d) * LDW + m] = h;
            sAl[(r * D + d) * LDW + m] = __float2bfloat16(w - __bfloat162float(h));
        }
    }
    #pragma unroll 1
    for (int i = tid; i < MUL * K / 8; i += 256) {
        int o = i / (K / 8), q = i - o * (K / 8);
        *(uint4*)(sWh + o * LDW + 8 * q) = *(const uint4*)(g_wshi + WOFF + o * K + 8 * q);
        *(uint4*)(sWl + o * LDW + 8 * q) = *(const uint4*)(g_wslo + WOFF + o * K + 8 * q);
    }
    __syncthreads();

    const int wr = (warp / WGC) * WM * 16;
    const int wc = (warp % WGC) * WN * 16;

    wmma::fragment<wmma::accumulator, 16, 16, 16, float> acc[WM][WN];
    #pragma unroll
    for (int m = 0; m < WM; m++)
        #pragma unroll
        for (int n = 0; n < WN; n++)
            wmma::fill_fragment(acc[m][n], 0.0f);

    #pragma unroll
    for (int ks = 0; ks < KS; ks++) {
        wmma::fragment<wmma::matrix_b, 16, 16, 16, __nv_bfloat16, wmma::col_major> bh[WN], bl[WN];
        #pragma unroll
        for (int n = 0; n < WN; n++) {
            wmma::load_matrix_sync(bh[n], sWh + (wc + 16 * n) * LDW + 16 * ks, LDW);
            wmma::load_matrix_sync(bl[n], sWl + (wc + 16 * n) * LDW + 16 * ks, LDW);
        }
        #pragma unroll
        for (int m = 0; m < WM; m++) {
            wmma::fragment<wmma::matrix_a, 16, 16, 16, __nv_bfloat16, wmma::row_major> ah, al;
            wmma::load_matrix_sync(ah, sAh + (wr + 16 * m) * LDW + 16 * ks, LDW);
            wmma::load_matrix_sync(al, sAl + (wr + 16 * m) * LDW + 16 * ks, LDW);
            #pragma unroll
            for (int n = 0; n < WN; n++) {
                wmma::mma_sync(acc[m][n], ah, bh[n], acc[m][n]);
                wmma::mma_sync(acc[m][n], ah, bl[n], acc[m][n]);
                wmma::mma_sync(acc[m][n], al, bh[n], acc[m][n]);
            }
        }
    }
    __syncthreads();

    float* Os = smem + F_AH;
    #pragma unroll
    for (int m = 0; m < WM; m++)
        #pragma unroll
        for (int n = 0; n < WN; n++)
            wmma::store_matrix_sync(Os + (wr + 16 * m) * LDO + wc + 16 * n,
                                    acc[m][n], LDO, wmma::mem_row_major);
    __syncthreads();

    const float* bias_s = smem;
    #pragma unroll 1
    for (int i = tid; i < nrows * SEGF4; i += 256) {
        int r = i / SEGF4, q = i - r * SEGF4;
        int j = 4 * q;
        float vv[4];
        #pragma unroll
        for (int e = 0; e < 4; e++) {
            int jj = j + e;
            int o  = jj / D;
            int d  = jj - o * D;
            vv[e] = Os[(r * D + d) * LDO + o] + bias_s[o];
        }
        float4 v; v.x = vv[0]; v.y = vv[1]; v.z = vv[2]; v.w = vv[3];
        *(float4*)(out + (size_t)(r0 + r) * ROWLEN + IN_OFF + 4 * q) = v;
    }
}

// ===================== seg3: FFMA2 (unchanged) =====================
template<int MUL, int D, int R, int NW, int CW, int TO, int KPH,
         int IN_OFF, int WOFF, bool ACT, int MINB>
__global__ __launch_bounds__(NW * 32, MINB)
void seg_s0(const float* __restrict__ x, const float* __restrict__ bias,
            float* __restrict__ out, int N) {
    constexpr int NT     = NW * 32;
    constexpr int K      = MUL;
    constexpr int KCH    = K / KPH;
    constexpr int SEGLEN = MUL * D;
    constexpr int SEGF4  = SEGLEN / 4;
    constexpr int CBLK   = R * D;
    constexpr int OW     = NW / CW;
    constexpr int CPW    = CBLK / CW;
    constexpr int TC     = CPW / 32;
    constexpr int TOH    = TO / 2;
    constexpr int TOQ    = TO / 4;
    constexpr int P      = SEGLEN + ((32 + D - (SEGLEN % 32)) % 32);

    float* Ws = smem;
    float* Xs = smem + KCH * MUL;
    float* Os = Xs;

    const int tid = threadIdx.x, lane = tid & 31, warp = tid >> 5;
    const int r0 = blockIdx.x * R;
    const int nrows = min(R, N - r0);
    const int ob = (warp % OW) * TO;
    const int cbase = (warp / OW) * CPW + lane;

    const int nld = nrows * SEGF4;
    #pragma unroll 1
    for (int i = tid; i < nld; i += NT) {
        int r = i / SEGF4, q = i - r * SEGF4;
        float4 v = *(const float4*)(x + (size_t)(r0 + r) * ROWLEN + IN_OFF + 4 * q);
        float* dst = Xs + r * P + 4 * q;
        dst[0] = v.x; dst[1] = v.y; dst[2] = v.z; dst[3] = v.w;
    }

    int bx[TC];
    #pragma unroll
    for (int i = 0; i < TC; i++) {
        int c = cbase + 32 * i;
        bx[i] = (c / D) * P + (c % D);
    }

    u64 acc[TC][TOH];
    #pragma unroll
    for (int p = 0; p < TOH; p++) {
        u64 bp = pack2(__ldg(bias + ob + 2 * p), __ldg(bias + ob + 2 * p + 1));
        #pragma unroll
        for (int i = 0; i < TC; i++) acc[i][p] = bp;
    }

    #pragma unroll
    for (int ph = 0; ph < KPH; ph++) {
        if (ph) __syncthreads();
        #pragma unroll 1
        for (int i = tid; i < KCH * MUL / 4; i += NT)
            ((float4*)Ws)[i] = ((const float4*)(g_wt + WOFF + ph * KCH * MUL))[i];
        __syncthreads();

        #pragma unroll 8
        for (int kl = 0; kl < KCH; kl++) {
            int k = ph * KCH + kl;
            u64 xd[TC];
            #pragma unroll
            for (int i = 0; i < TC; i++) {
                float xv = Xs[bx[i] + k * D];
                xd[i] = pack2(xv, xv);
            }
            const ulonglong2* wq = (const ulonglong2*)(Ws + kl * MUL + ob);
            #pragma unroll
            for (int j = 0; j < TOQ; j++) {
                ulonglong2 w2 = wq[j];
                #pragma unroll
                for (int i = 0; i < TC; i++) {
                    acc[i][2 * j]     = ffma2(xd[i], w2.x, acc[i][2 * j]);
                    acc[i][2 * j + 1] = ffma2(xd[i], w2.y, acc[i][2 * j + 1]);
                }
            }
        }
    }
    __syncthreads();

    #pragma unroll
    for (int i = 0; i < TC; i++) {
        int c = cbase + 32 * i;
        float* od = Os + (c / D) * P + (c % D);
        #pragma unroll
        for (int p = 0; p < TOH; p++) {
            float lo, hi; unpack2(acc[i][p], lo, hi);
            od[(ob + 2 * p) * D]     = lo;
            od[(ob + 2 * p + 1) * D] = hi;
        }
    }
    __syncthreads();

    #pragma unroll 1
    for (int i = tid; i < nld; i += NT) {
        int r = i / SEGF4, q = i - r * SEGF4;
        const float* src = Os + r * P + 4 * q;
        float4 v;
        v.x = src[0]; v.y = src[1]; v.z = src[2]; v.w = src[3];
        *(float4*)(out + (size_t)(r0 + r) * ROWLEN + IN_OFF + 4 * q) = v;
    }
}

constexpr int pitch_of(int seglen, int d) {
    return seglen + ((32 + d - (seglen % 32)) % 32);
}

// ---- streams/events for fork-join overlap inside the captured graph ----
static cudaStream_t g_side[3];
static cudaEvent_t  g_ev_root;
static cudaEvent_t  g_ev_done[3];
static bool         g_init_done = false;

extern "C" void kernel_launch(void* const* d_in, const int* in_sizes, int n_in,
                              void* d_out, int out_size) {
    const float* x  = (const float*)d_in[0];
    const float* w0 = (const float*)d_in[1];
    const float* w1 = (const float*)d_in[2];
    const float* w2 = (const float*)d_in[3];
    const float* w3 = (const float*)d_in[4];
    const float* b0 = (const float*)d_in[5];
    const float* b1 = (const float*)d_in[6];
    const float* b2 = (const float*)d_in[7];
    const float* b3 = (const float*)d_in[8];
    float* out = (float*)d_out;
    const int N = in_sizes[0] / ROWLEN;

    if (!g_init_done) {
        for (int i = 0; i < 3; i++)
            cudaStreamCreateWithFlags(&g_side[i], cudaStreamNonBlocking);
        cudaEventCreateWithFlags(&g_ev_root, cudaEventDisableTiming);
        for (int i = 0; i < 3; i++)
            cudaEventCreateWithFlags(&g_ev_done[i], cudaEventDisableTiming);
        g_init_done = true;
    }

    // seg1: MUL=64, D=3, R=32 -> GROWS=96=GPAD: RT=6; warps 2x4 -> WM=3, WN=1
    auto k1 = seg_wmma<64, 3, 32,  96, 2, 4, 128,    0, 4>;
    // seg2: MUL=32, D=5, R=32 -> GROWS=160, GPAD=192: RT=12; warps 4x2 -> WM=3, WN=1
    auto k2 = seg_wmma<32, 5, 32, 192, 4, 2, 320, 4096, 4>;
    // seg3: FFMA2
    auto k3 = seg_s0< 16, 7, 32, 4, 1, 4, 1, 480, 21504, false, 8>;

    constexpr int SM1 = (64 + 2 * (96 * 72 / 2)  + 2 * (64 * 72 / 2)) * 4;   // 46336
    constexpr int SM2 = (32 + 2 * (192 * 40 / 2) + 2 * (32 * 40 / 2)) * 4;   // 35968
    constexpr int S3  = (16 * 16 + 32 * pitch_of(112, 7)) * 4;               // 18304

    cudaFuncSetAttribute(seg0_wmma, cudaFuncAttributeMaxDynamicSharedMemorySize, SM0_BYTES);
    cudaFuncSetAttribute(k1, cudaFuncAttributeMaxDynamicSharedMemorySize, SM1);
    cudaFuncSetAttribute(k2, cudaFuncAttributeMaxDynamicSharedMemorySize, SM2);
    cudaFuncSetAttribute(k3, cudaFuncAttributeMaxDynamicSharedMemorySize, S3);

    // ---- prep on main stream, then fork ----
    prep_w0<<<64, 256>>>(w0);
    prep_ws<<<20, 256>>>(w1, w2);
    prep_w3<<<1, 256>>>(w3);
    cudaEventRecord(g_ev_root, 0);
    for (int i = 0; i < 3; i++)
        cudaStreamWaitEvent(g_side[i], g_ev_root, 0);

    const int g64 = (N + 63) / 64;   // 1563
    const int g32 = (N + 31) / 32;   // 3125

    seg0_wmma<<<g64 * 2, 256, SM0_BYTES>>>(x, b0, out, N);   // main stream
    k1<<<g32, 256, SM1, g_side[0]>>>(x, b1, out, N);
    k2<<<g32, 256, SM2, g_side[1]>>>(x, b2, out, N);
    k3<<<g32, 128, S3,  g_side[2]>>>(x, b3, out, N);

    // ---- join back onto the main (capture) stream ----
    for (int i = 0; i < 3; i++) {
        cudaEventRecord(g_ev_done[i], g_side[i]);
        cudaStreamWaitEvent(0, g_ev_done[i], 0);
    }
}

// round 16
// speedup vs baseline: 1.0391x; 1.0391x over previous
#include <cuda_runtime.h>
#include <cuda_bf16.h>
#include <mma.h>
#include <cstdint>

using namespace nvcuda;

typedef unsigned long long u64;
#define DEVINL __device__ __forceinline__

DEVINL u64 pack2(float lo, float hi) {
    u64 d;
    asm("mov.b64 %0, {%1, %2};" : "=l"(d) : "f"(lo), "f"(hi));
    return d;
}
DEVINL void unpack2(u64 v, float& lo, float& hi) {
    asm("mov.b64 {%0, %1}, %2;" : "=f"(lo), "=f"(hi) : "l"(v));
}
DEVINL u64 ffma2(u64 a, u64 b, u64 c) {
    u64 d;
    asm("fma.rn.f32x2 %0, %1, %2, %3;" : "=l"(d) : "l"(a), "l"(b), "l"(c));
    return d;
}

// smooth_leaky_relu(x) = 0.6x + 0.4x*tanh(x/2)   (alpha=0.2)
DEVINL float act_fn(float v) {
    float t;
    asm("tanh.approx.f32 %0, %1;" : "=f"(t) : "f"(0.5f * v));
    return v * (0.6f + 0.4f * t);
}

static constexpr int ROWLEN = 592;

extern __shared__ float smem[];

// ===================== weights scratch =====================
__device__ float g_wt[21760];                 // fp32 [k][o] (only seg3 range used)
__device__ __nv_bfloat16 g_w0hi[16384];       // seg0 W0 bf16 hi/lo, natural [o][k]
__device__ __nv_bfloat16 g_w0lo[16384];
__device__ __nv_bfloat16 g_wshi[5120];        // seg1 [0,4096) + seg2 [4096,5120)
__device__ __nv_bfloat16 g_wslo[5120];
__device__ __nv_bfloat16 g_bb[2048];          // seg0 bias tile [o][16]: lane0=hi, lane1=lo

__global__ void prep_w0(const float* __restrict__ w0) {
    int idx = blockIdx.x * 256 + threadIdx.x;
    if (idx >= 16384) return;
    float w = w0[idx];
    __nv_bfloat16 h = __float2bfloat16(w);
    g_w0hi[idx] = h;
    g_w0lo[idx] = __float2bfloat16(w - __bfloat162float(h));
}

__global__ void prep_ws(const float* __restrict__ w1, const float* __restrict__ w2) {
    int idx = blockIdx.x * 256 + threadIdx.x;
    if (idx >= 5120) return;
    float w = (idx < 4096) ? w1[idx] : w2[idx - 4096];
    __nv_bfloat16 h = __float2bfloat16(w);
    g_wshi[idx] = h;
    g_wslo[idx] = __float2bfloat16(w - __bfloat162float(h));
}

__global__ void prep_w3(const float* __restrict__ w3) {
    int t = threadIdx.x;           // 256 entries: [k][o]
    int k = t >> 4, o = t & 15;
    g_wt[21504 + t] = w3[o * 16 + k];
}

__global__ void prep_bb(const float* __restrict__ b0) {
    int i = blockIdx.x * 256 + threadIdx.x;
    if (i >= 2048) return;
    int o = i >> 4, l = i & 15;
    float b = b0[o];
    __nv_bfloat16 h = __float2bfloat16(b);
    __nv_bfloat16 v = __float2bfloat16(0.f);
    if (l == 0) v = h;
    else if (l == 1) v = __float2bfloat16(b - __bfloat162float(h));
    g_bb[i] = v;
}

// ===================== seg0: wmma bf16-split GEMM, 64x128 tile, bias-in-GEMM =====================
static constexpr int LDA0 = 72;     // bf16 pitch (A and W tiles)
static constexpr int LDB0 = 24;     // bf16 pitch (ones / bias tiles)
static constexpr int LDO0 = 132;    // f32 pitch (tail staging only)
// float offsets
static constexpr int F_AH0 = 0;                   // 64*72/2 = 2304
static constexpr int F_AL0 = F_AH0 + 2304;
static constexpr int F_WH0 = F_AL0 + 2304;        // 128*72/2 = 4608
static constexpr int F_WL0 = F_WH0 + 4608;
static constexpr int F_ONE = F_WL0 + 4608;        // 16*24/2 = 192
static constexpr int F_BB0 = F_ONE + 192;         // 128*24/2 = 1536
static constexpr int SM0_BYTES = (F_BB0 + 1536) * 4;   // 62208

__global__ __launch_bounds__(256, 3)
void seg0_wmma(const float* __restrict__ x, float* __restrict__ out, int N) {
    const int tid = threadIdx.x, warp = tid >> 5;
    const int r0 = blockIdx.x * 64;

    __nv_bfloat16* sAh = (__nv_bfloat16*)(smem + F_AH0);
    __nv_bfloat16* sAl = (__nv_bfloat16*)(smem + F_AL0);
    __nv_bfloat16* sWh = (__nv_bfloat16*)(smem + F_WH0);
    __nv_bfloat16* sWl = (__nv_bfloat16*)(smem + F_WL0);
    __nv_bfloat16* sOne = (__nv_bfloat16*)(smem + F_ONE);
    __nv_bfloat16* sBb  = (__nv_bfloat16*)(smem + F_BB0);

    // ---- one-time: ones tile (k-lanes 0,1 = 1) + bias tile ----
    #pragma unroll 1
    for (int i = tid; i < 16 * LDB0; i += 256) {
        int cc = i % LDB0;
        sOne[i] = __float2bfloat16((cc < 2) ? 1.f : 0.f);
    }
    #pragma unroll 1
    for (int i = tid; i < 2048; i += 256) {
        int o = i >> 4, l = i & 15;
        sBb[o * LDB0 + l] = g_bb[i];
    }

    const int wrow = (warp >> 2) * 32;   // 0 or 32
    const int wcol = (warp & 3) * 32;    // 0,32,64,96

    wmma::fragment<wmma::accumulator, 16, 16, 16, float> acc[2][2];
    #pragma unroll
    for (int m = 0; m < 2; m++)
        #pragma unroll
        for (int n = 0; n < 2; n++)
            wmma::fill_fragment(acc[m][n], 0.0f);

    #pragma unroll 1
    for (int c = 0; c < 2; c++) {
        __syncthreads();
        // ---- stage A chunk: 64 rows x 64 k, bf16 hi/lo split ----
        #pragma unroll 1
        for (int i = tid; i < 64 * 16; i += 256) {
            int row = i >> 4, q = i & 15;
            float4 v = make_float4(0.f, 0.f, 0.f, 0.f);
            if (r0 + row < N)
                v = *(const float4*)(x + (size_t)(r0 + row) * ROWLEN + 64 * c + 4 * q);
            __nv_bfloat16 h0 = __float2bfloat16(v.x), h1 = __float2bfloat16(v.y);
            __nv_bfloat16 h2 = __float2bfloat16(v.z), h3 = __float2bfloat16(v.w);
            float l0 = v.x - __bfloat162float(h0), l1 = v.y - __bfloat162float(h1);
            float l2 = v.z - __bfloat162float(h2), l3 = v.w - __bfloat162float(h3);
            __nv_bfloat162 hp0 = __halves2bfloat162(h0, h1);
            __nv_bfloat162 hp1 = __halves2bfloat162(h2, h3);
            __nv_bfloat162 lp0 = __floats2bfloat162_rn(l0, l1);
            __nv_bfloat162 lp1 = __floats2bfloat162_rn(l2, l3);
            uint2 uh; uh.x = *(uint32_t*)&hp0; uh.y = *(uint32_t*)&hp1;
            uint2 ul; ul.x = *(uint32_t*)&lp0; ul.y = *(uint32_t*)&lp1;
            *(uint2*)(sAh + row * LDA0 + 4 * q) = uh;
            *(uint2*)(sAl + row * LDA0 + 4 * q) = ul;
        }
        // ---- stage W chunk: 128 o x 64 k (pre-split bf16) ----
        #pragma unroll 1
        for (int i = tid; i < 128 * 8; i += 256) {
            int o = i >> 3, q = i & 7;
            *(uint4*)(sWh + o * LDA0 + 8 * q) = *(const uint4*)(g_w0hi + o * 128 + 64 * c + 8 * q);
            *(uint4*)(sWl + o * LDA0 + 8 * q) = *(const uint4*)(g_w0lo + o * 128 + 64 * c + 8 * q);
        }
        __syncthreads();

        #pragma unroll
        for (int ks = 0; ks < 4; ks++) {
            wmma::fragment<wmma::matrix_b, 16, 16, 16, __nv_bfloat16, wmma::col_major> bh[2], bl[2];
            #pragma unroll
            for (int n = 0; n < 2; n++) {
                wmma::load_matrix_sync(bh[n], sWh + (wcol + 16 * n) * LDA0 + 16 * ks, LDA0);
                wmma::load_matrix_sync(bl[n], sWl + (wcol + 16 * n) * LDA0 + 16 * ks, LDA0);
            }
            #pragma unroll
            for (int m = 0; m < 2; m++) {
                wmma::fragment<wmma::matrix_a, 16, 16, 16, __nv_bfloat16, wmma::row_major> ah, al;
                wmma::load_matrix_sync(ah, sAh + (wrow + 16 * m) * LDA0 + 16 * ks, LDA0);
                wmma::load_matrix_sync(al, sAl + (wrow + 16 * m) * LDA0 + 16 * ks, LDA0);
                #pragma unroll
                for (int n = 0; n < 2; n++) {
                    wmma::mma_sync(acc[m][n], ah, bh[n], acc[m][n]);
                    wmma::mma_sync(acc[m][n], ah, bl[n], acc[m][n]);
                    wmma::mma_sync(acc[m][n], al, bh[n], acc[m][n]);
                }
            }
        }
    }

    // ---- bias via GEMM: acc += Ones(16x16, lanes0-1) x Bias(hi|lo) ----
    {
        wmma::fragment<wmma::matrix_a, 16, 16, 16, __nv_bfloat16, wmma::row_major> aone;
        wmma::load_matrix_sync(aone, sOne, LDB0);
        #pragma unroll
        for (int n = 0; n < 2; n++) {
            wmma::fragment<wmma::matrix_b, 16, 16, 16, __nv_bfloat16, wmma::col_major> bb;
            wmma::load_matrix_sync(bb, sBb + (wcol + 16 * n) * LDB0, LDB0);
            #pragma unroll
            for (int m = 0; m < 2; m++)
                wmma::mma_sync(acc[m][n], aone, bb, acc[m][n]);
        }
    }

    // ---- activation in-fragment (elementwise) ----
    #pragma unroll
    for (int m = 0; m < 2; m++)
        #pragma unroll
        for (int n = 0; n < 2; n++)
            #pragma unroll
            for (int e = 0; e < acc[m][n].num_elements; e++)
                acc[m][n].x[e] = act_fn(acc[m][n].x[e]);

    if (r0 + 64 <= N) {
        // ---- full block: direct fragment store to gmem (ld=592) ----
        #pragma unroll
        for (int m = 0; m < 2; m++)
            #pragma unroll
            for (int n = 0; n < 2; n++)
                wmma::store_matrix_sync(out + (size_t)(r0 + wrow + 16 * m) * ROWLEN + wcol + 16 * n,
                                        acc[m][n], ROWLEN, wmma::mem_row_major);
    } else {
        // ---- tail block: stage to smem, guarded copy ----
        __syncthreads();
        float* Os = smem;   // 64*132 = 8448 floats, overlays A/W staging (done with it)
        #pragma unroll
        for (int m = 0; m < 2; m++)
            #pragma unroll
            for (int n = 0; n < 2; n++)
                wmma::store_matrix_sync(Os + (wrow + 16 * m) * LDO0 + wcol + 16 * n,
                                        acc[m][n], LDO0, wmma::mem_row_major);
        __syncthreads();
        #pragma unroll 1
        for (int i = tid; i < 64 * 32; i += 256) {
            int row = i >> 5, q = i & 31;
            if (r0 + row < N) {
                const float* src = Os + row * LDO0 + 4 * q;
                float4 v; v.x = src[0]; v.y = src[1]; v.z = src[2]; v.w = src[3];
                *(float4*)(out + (size_t)(r0 + row) * ROWLEN + 4 * q) = v;
            }
        }
    }
}

// ===================== generic interleaved wmma kernel (seg1/seg2, R15 unchanged) =====================
template<int MUL, int D, int R, int GPAD, int WGR, int WGC, int IN_OFF, int WOFF, int MINB>
__global__ __launch_bounds__(256, MINB)
void seg_wmma(const float* __restrict__ x, const float* __restrict__ bias,
              float* __restrict__ out, int N) {
    constexpr int K      = MUL;
    constexpr int GROWS  = R * D;
    constexpr int SEGLEN = MUL * D;
    constexpr int SEGF4  = SEGLEN / 4;
    constexpr int LDW    = K + 8;
    constexpr int LDO    = MUL + 4;
    constexpr int RT     = GPAD / 16;
    constexpr int CT     = MUL / 16;
    constexpr int WM     = RT / WGR;
    constexpr int WN     = CT / WGC;
    constexpr int KS     = K / 16;
    constexpr int ASZ    = GPAD * LDW / 2;
    constexpr int WSZ    = MUL * LDW / 2;
    constexpr int F_AH   = MUL;
    constexpr int F_AL   = F_AH + ASZ;
    constexpr int F_WH   = F_AL + ASZ;
    constexpr int F_WL   = F_WH + WSZ;
    static_assert(WGR * WGC == 8, "");
    static_assert(RT % WGR == 0 && CT % WGC == 0, "");
    static_assert(GPAD % 16 == 0 && GPAD >= GROWS, "");

    const int tid = threadIdx.x, warp = tid >> 5;
    const int r0 = blockIdx.x * R;
    const int nrows = min(R, N - r0);

    __nv_bfloat16* sAh = (__nv_bfloat16*)(smem + F_AH);
    __nv_bfloat16* sAl = (__nv_bfloat16*)(smem + F_AL);
    __nv_bfloat16* sWh = (__nv_bfloat16*)(smem + F_WH);
    __nv_bfloat16* sWl = (__nv_bfloat16*)(smem + F_WL);

    if (tid < MUL) smem[tid] = bias[tid];

    if (GPAD > GROWS) {
        constexpr int PADW = (GPAD - GROWS) * LDW / 2;
        uint32_t* ph = (uint32_t*)(sAh + GROWS * LDW);
        uint32_t* pl = (uint32_t*)(sAl + GROWS * LDW);
        #pragma unroll 1
        for (int i = tid; i < PADW; i += 256) { ph[i] = 0; pl[i] = 0; }
    }

    #pragma unroll 1
    for (int i = tid; i < R * SEGF4; i += 256) {
        int r = i / SEGF4, q = i - r * SEGF4;
        float4 v = make_float4(0.f, 0.f, 0.f, 0.f);
        if (r0 + r < N)
            v = *(const float4*)(x + (size_t)(r0 + r) * ROWLEN + IN_OFF + 4 * q);
        float vv[4] = {v.x, v.y, v.z, v.w};
        int j = 4 * q;
        #pragma unroll
        for (int e = 0; e < 4; e++) {
            int jj = j + e;
            int m  = jj / D;
            int d  = jj - m * D;
            float w = vv[e];
            __nv_bfloat16 h = __float2bfloat16(w);
            sAh[(r * D + d) * LDW + m] = h;
            sAl[(r * D + d) * LDW + m] = __float2bfloat16(w - __bfloat162float(h));
        }
    }
    #pragma unroll 1
    for (int i = tid; i < MUL * K / 8; i += 256) {
        int o = i / (K / 8), q = i - o * (K / 8);
        *(uint4*)(sWh + o * LDW + 8 * q) = *(const uint4*)(g_wshi + WOFF + o * K + 8 * q);
        *(uint4*)(sWl + o * LDW + 8 * q) = *(const uint4*)(g_wslo + WOFF + o * K + 8 * q);
    }
    __syncthreads();

    const int wr = (warp / WGC) * WM * 16;
    const int wc = (warp % WGC) * WN * 16;

    wmma::fragment<wmma::accumulator, 16, 16, 16, float> acc[WM][WN];
    #pragma unroll
    for (int m = 0; m < WM; m++)
        #pragma unroll
        for (int n = 0; n < WN; n++)
            wmma::fill_fragment(acc[m][n], 0.0f);

    #pragma unroll
    for (int ks = 0; ks < KS; ks++) {
        wmma::fragment<wmma::matrix_b, 16, 16, 16, __nv_bfloat16, wmma::col_major> bh[WN], bl[WN];
        #pragma unroll
        for (int n = 0; n < WN; n++) {
            wmma::load_matrix_sync(bh[n], sWh + (wc + 16 * n) * LDW + 16 * ks, LDW);
            wmma::load_matrix_sync(bl[n], sWl + (wc + 16 * n) * LDW + 16 * ks, LDW);
        }
        #pragma unroll
        for (int m = 0; m < WM; m++) {
            wmma::fragment<wmma::matrix_a, 16, 16, 16, __nv_bfloat16, wmma::row_major> ah, al;
            wmma::load_matrix_sync(ah, sAh + (wr + 16 * m) * LDW + 16 * ks, LDW);
            wmma::load_matrix_sync(al, sAl + (wr + 16 * m) * LDW + 16 * ks, LDW);
            #pragma unroll
            for (int n = 0; n < WN; n++) {
                wmma::mma_sync(acc[m][n], ah, bh[n], acc[m][n]);
                wmma::mma_sync(acc[m][n], ah, bl[n], acc[m][n]);
                wmma::mma_sync(acc[m][n], al, bh[n], acc[m][n]);
            }
        }
    }
    __syncthreads();

    float* Os = smem + F_AH;
    #pragma unroll
    for (int m = 0; m < WM; m++)
        #pragma unroll
        for (int n = 0; n < WN; n++)
            wmma::store_matrix_sync(Os + (wr + 16 * m) * LDO + wc + 16 * n,
                                    acc[m][n], LDO, wmma::mem_row_major);
    __syncthreads();

    const float* bias_s = smem;
    #pragma unroll 1
    for (int i = tid; i < nrows * SEGF4; i += 256) {
        int r = i / SEGF4, q = i - r * SEGF4;
        int j = 4 * q;
        float vv[4];
        #pragma unroll
        for (int e = 0; e < 4; e++) {
            int jj = j + e;
            int o  = jj / D;
            int d  = jj - o * D;
            vv[e] = Os[(r * D + d) * LDO + o] + bias_s[o];
        }
        float4 v; v.x = vv[0]; v.y = vv[1]; v.z = vv[2]; v.w = vv[3];
        *(float4*)(out + (size_t)(r0 + r) * ROWLEN + IN_OFF + 4 * q) = v;
    }
}

// ===================== seg3: FFMA2 (unchanged) =====================
template<int MUL, int D, int R, int NW, int CW, int TO, int KPH,
         int IN_OFF, int WOFF, bool ACT, int MINB>
__global__ __launch_bounds__(NW * 32, MINB)
void seg_s0(const float* __restrict__ x, const float* __restrict__ bias,
            float* __restrict__ out, int N) {
    constexpr int NT     = NW * 32;
    constexpr int K      = MUL;
    constexpr int KCH    = K / KPH;
    constexpr int SEGLEN = MUL * D;
    constexpr int SEGF4  = SEGLEN / 4;
    constexpr int CBLK   = R * D;
    constexpr int OW     = NW / CW;
    constexpr int CPW    = CBLK / CW;
    constexpr int TC     = CPW / 32;
    constexpr int TOH    = TO / 2;
    constexpr int TOQ    = TO / 4;
    constexpr int P      = SEGLEN + ((32 + D - (SEGLEN % 32)) % 32);

    float* Ws = smem;
    float* Xs = smem + KCH * MUL;
    float* Os = Xs;

    const int tid = threadIdx.x, lane = tid & 31, warp = tid >> 5;
    const int r0 = blockIdx.x * R;
    const int nrows = min(R, N - r0);
    const int ob = (warp % OW) * TO;
    const int cbase = (warp / OW) * CPW + lane;

    const int nld = nrows * SEGF4;
    #pragma unroll 1
    for (int i = tid; i < nld; i += NT) {
        int r = i / SEGF4, q = i - r * SEGF4;
        float4 v = *(const float4*)(x + (size_t)(r0 + r) * ROWLEN + IN_OFF + 4 * q);
        float* dst = Xs + r * P + 4 * q;
        dst[0] = v.x; dst[1] = v.y; dst[2] = v.z; dst[3] = v.w;
    }

    int bx[TC];
    #pragma unroll
    for (int i = 0; i < TC; i++) {
        int c = cbase + 32 * i;
        bx[i] = (c / D) * P + (c % D);
    }

    u64 acc[TC][TOH];
    #pragma unroll
    for (int p = 0; p < TOH; p++) {
        u64 bp = pack2(__ldg(bias + ob + 2 * p), __ldg(bias + ob + 2 * p + 1));
        #pragma unroll
        for (int i = 0; i < TC; i++) acc[i][p] = bp;
    }

    #pragma unroll
    for (int ph = 0; ph < KPH; ph++) {
        if (ph) __syncthreads();
        #pragma unroll 1
        for (int i = tid; i < KCH * MUL / 4; i += NT)
            ((float4*)Ws)[i] = ((const float4*)(g_wt + WOFF + ph * KCH * MUL))[i];
        __syncthreads();

        #pragma unroll 8
        for (int kl = 0; kl < KCH; kl++) {
            int k = ph * KCH + kl;
            u64 xd[TC];
            #pragma unroll
            for (int i = 0; i < TC; i++) {
                float xv = Xs[bx[i] + k * D];
                xd[i] = pack2(xv, xv);
            }
            const ulonglong2* wq = (const ulonglong2*)(Ws + kl * MUL + ob);
            #pragma unroll
            for (int j = 0; j < TOQ; j++) {
                ulonglong2 w2 = wq[j];
                #pragma unroll
                for (int i = 0; i < TC; i++) {
                    acc[i][2 * j]     = ffma2(xd[i], w2.x, acc[i][2 * j]);
                    acc[i][2 * j + 1] = ffma2(xd[i], w2.y, acc[i][2 * j + 1]);
                }
            }
        }
    }
    __syncthreads();

    #pragma unroll
    for (int i = 0; i < TC; i++) {
        int c = cbase + 32 * i;
        float* od = Os + (c / D) * P + (c % D);
        #pragma unroll
        for (int p = 0; p < TOH; p++) {
            float lo, hi; unpack2(acc[i][p], lo, hi);
            od[(ob + 2 * p) * D]     = lo;
            od[(ob + 2 * p + 1) * D] = hi;
        }
    }
    __syncthreads();

    #pragma unroll 1
    for (int i = tid; i < nld; i += NT) {
        int r = i / SEGF4, q = i - r * SEGF4;
        const float* src = Os + r * P + 4 * q;
        float4 v;
        v.x = src[0]; v.y = src[1]; v.z = src[2]; v.w = src[3];
        *(float4*)(out + (size_t)(r0 + r) * ROWLEN + IN_OFF + 4 * q) = v;
    }
}

constexpr int pitch_of(int seglen, int d) {
    return seglen + ((32 + d - (seglen % 32)) % 32);
}

// ---- streams/events for fork-join overlap inside the captured graph ----
static cudaStream_t g_side[3];
static cudaEvent_t  g_ev_root;
static cudaEvent_t  g_ev_done[3];
static bool         g_init_done = false;

extern "C" void kernel_launch(void* const* d_in, const int* in_sizes, int n_in,
                              void* d_out, int out_size) {
    const float* x  = (const float*)d_in[0];
    const float* w0 = (const float*)d_in[1];
    const float* w1 = (const float*)d_in[2];
    const float* w2 = (const float*)d_in[3];
    const float* w3 = (const float*)d_in[4];
    const float* b0 = (const float*)d_in[5];
    const float* b1 = (const float*)d_in[6];
    const float* b2 = (const float*)d_in[7];
    const float* b3 = (const float*)d_in[8];
    float* out = (float*)d_out;
    const int N = in_sizes[0] / ROWLEN;

    if (!g_init_done) {
        for (int i = 0; i < 3; i++)
            cudaStreamCreateWithFlags(&g_side[i], cudaStreamNonBlocking);
        cudaEventCreateWithFlags(&g_ev_root, cudaEventDisableTiming);
        for (int i = 0; i < 3; i++)
            cudaEventCreateWithFlags(&g_ev_done[i], cudaEventDisableTiming);
        g_init_done = true;
    }

    // seg1: MUL=64, D=3, R=32 -> GROWS=96=GPAD: RT=6; warps 2x4 -> WM=3, WN=1
    auto k1 = seg_wmma<64, 3, 32,  96, 2, 4, 128,    0, 4>;
    // seg2: MUL=32, D=5, R=32 -> GROWS=160, GPAD=192: RT=12; warps 4x2 -> WM=3, WN=1
    auto k2 = seg_wmma<32, 5, 32, 192, 4, 2, 320, 4096, 4>;
    // seg3: FFMA2
    auto k3 = seg_s0< 16, 7, 32, 4, 1, 4, 1, 480, 21504, false, 8>;

    constexpr int SM1 = (64 + 2 * (96 * 72 / 2)  + 2 * (64 * 72 / 2)) * 4;   // 46336
    constexpr int SM2 = (32 + 2 * (192 * 40 / 2) + 2 * (32 * 40 / 2)) * 4;   // 35968
    constexpr int S3  = (16 * 16 + 32 * pitch_of(112, 7)) * 4;               // 18304

    cudaFuncSetAttribute(seg0_wmma, cudaFuncAttributeMaxDynamicSharedMemorySize, SM0_BYTES);
    cudaFuncSetAttribute(k1, cudaFuncAttributeMaxDynamicSharedMemorySize, SM1);
    cudaFuncSetAttribute(k2, cudaFuncAttributeMaxDynamicSharedMemorySize, SM2);
    cudaFuncSetAttribute(k3, cudaFuncAttributeMaxDynamicSharedMemorySize, S3);

    // ---- prep on main stream, then fork ----
    prep_w0<<<64, 256>>>(w0);
    prep_ws<<<20, 256>>>(w1, w2);
    prep_w3<<<1, 256>>>(w3);
    prep_bb<<<8, 256>>>(b0);
    cudaEventRecord(g_ev_root, 0);
    for (int i = 0; i < 3; i++)
        cudaStreamWaitEvent(g_side[i], g_ev_root, 0);

    const int g64 = (N + 63) / 64;   // 1563
    const int g32 = (N + 31) / 32;   // 3125

    seg0_wmma<<<g64, 256, SM0_BYTES>>>(x, out, N);   // main stream
    k1<<<g32, 256, SM1, g_side[0]>>>(x, b1, out, N);
    k2<<<g32, 256, SM2, g_side[1]>>>(x, b2, out, N);
    k3<<<g32, 128, S3,  g_side[2]>>>(x, b3, out, N);

    // ---- join back onto the main (capture) stream ----
    for (int i = 0; i < 3; i++) {
        cudaEventRecord(g_ev_done[i], g_side[i]);
        cudaStreamWaitEvent(0, g_ev_done[i], 0);
    }
}

// round 17
// speedup vs baseline: 1.0472x; 1.0078x over previous
#include <cuda_runtime.h>
#include <cuda_bf16.h>
#include <mma.h>
#include <cstdint>

using namespace nvcuda;

typedef unsigned long long u64;
#define DEVINL __device__ __forceinline__

DEVINL u64 pack2(float lo, float hi) {
    u64 d;
    asm("mov.b64 %0, {%1, %2};" : "=l"(d) : "f"(lo), "f"(hi));
    return d;
}
DEVINL void unpack2(u64 v, float& lo, float& hi) {
    asm("mov.b64 {%0, %1}, %2;" : "=f"(lo), "=f"(hi) : "l"(v));
}
DEVINL u64 ffma2(u64 a, u64 b, u64 c) {
    u64 d;
    asm("fma.rn.f32x2 %0, %1, %2, %3;" : "=l"(d) : "l"(a), "l"(b), "l"(c));
    return d;
}

// smooth_leaky_relu(x) = 0.6x + 0.4x*tanh(x/2)   (alpha=0.2)
DEVINL float act_fn(float v) {
    float t;
    asm("tanh.approx.f32 %0, %1;" : "=f"(t) : "f"(0.5f * v));
    return v * (0.6f + 0.4f * t);
}

static constexpr int ROWLEN = 592;

extern __shared__ float smem[];

// ===================== weights scratch =====================
__device__ float g_wt[21760];                 // fp32 [k][o] (only seg3 range used)
__device__ __nv_bfloat16 g_w0hi[16384];       // seg0 W0 bf16 hi/lo, natural [o][k]
__device__ __nv_bfloat16 g_w0lo[16384];
__device__ __nv_bfloat16 g_wshi[5120];        // seg1 [0,4096) + seg2 [4096,5120)
__device__ __nv_bfloat16 g_wslo[5120];
__device__ __nv_bfloat16 g_bb[2048];          // seg0 bias tile [o][16]: lane0=hi, lane1=lo

// merged: W0 split + bias tile  (runs on main stream)
__global__ void prep_main(const float* __restrict__ w0, const float* __restrict__ b0) {
    int idx = blockIdx.x * 256 + threadIdx.x;
    if (idx < 16384) {
        float w = w0[idx];
        __nv_bfloat16 h = __float2bfloat16(w);
        g_w0hi[idx] = h;
        g_w0lo[idx] = __float2bfloat16(w - __bfloat162float(h));
    } else if (idx < 16384 + 2048) {
        int i = idx - 16384;
        int o = i >> 4, l = i & 15;
        float b = b0[o];
        __nv_bfloat16 h = __float2bfloat16(b);
        __nv_bfloat16 v = __float2bfloat16(0.f);
        if (l == 0) v = h;
        else if (l == 1) v = __float2bfloat16(b - __bfloat162float(h));
        g_bb[i] = v;
    }
}

__global__ void prep_s1(const float* __restrict__ w1) {
    int idx = blockIdx.x * 256 + threadIdx.x;
    if (idx >= 4096) return;
    float w = w1[idx];
    __nv_bfloat16 h = __float2bfloat16(w);
    g_wshi[idx] = h;
    g_wslo[idx] = __float2bfloat16(w - __bfloat162float(h));
}

__global__ void prep_s2(const float* __restrict__ w2) {
    int idx = blockIdx.x * 256 + threadIdx.x;
    if (idx >= 1024) return;
    float w = w2[idx];
    __nv_bfloat16 h = __float2bfloat16(w);
    g_wshi[4096 + idx] = h;
    g_wslo[4096 + idx] = __float2bfloat16(w - __bfloat162float(h));
}

__global__ void prep_s3(const float* __restrict__ w3) {
    int t = threadIdx.x;           // 256 entries: [k][o]
    int k = t >> 4, o = t & 15;
    g_wt[21504 + t] = w3[o * 16 + k];
}

// ===================== seg0: wmma bf16-split GEMM, 64x128 tile, bias-in-GEMM (R16) =====================
static constexpr int LDA0 = 72;     // bf16 pitch (A and W tiles)
static constexpr int LDB0 = 24;     // bf16 pitch (ones / bias tiles)
static constexpr int LDO0 = 132;    // f32 pitch (tail staging only)
static constexpr int F_AH0 = 0;                   // 64*72/2 = 2304
static constexpr int F_AL0 = F_AH0 + 2304;
static constexpr int F_WH0 = F_AL0 + 2304;        // 128*72/2 = 4608
static constexpr int F_WL0 = F_WH0 + 4608;
static constexpr int F_ONE = F_WL0 + 4608;        // 16*24/2 = 192
static constexpr int F_BB0 = F_ONE + 192;         // 128*24/2 = 1536
static constexpr int SM0_BYTES = (F_BB0 + 1536) * 4;   // 62208

__global__ __launch_bounds__(256, 3)
void seg0_wmma(const float* __restrict__ x, float* __restrict__ out, int N) {
    const int tid = threadIdx.x, warp = tid >> 5;
    const int r0 = blockIdx.x * 64;

    __nv_bfloat16* sAh = (__nv_bfloat16*)(smem + F_AH0);
    __nv_bfloat16* sAl = (__nv_bfloat16*)(smem + F_AL0);
    __nv_bfloat16* sWh = (__nv_bfloat16*)(smem + F_WH0);
    __nv_bfloat16* sWl = (__nv_bfloat16*)(smem + F_WL0);
    __nv_bfloat16* sOne = (__nv_bfloat16*)(smem + F_ONE);
    __nv_bfloat16* sBb  = (__nv_bfloat16*)(smem + F_BB0);

    #pragma unroll 1
    for (int i = tid; i < 16 * LDB0; i += 256) {
        int cc = i % LDB0;
        sOne[i] = __float2bfloat16((cc < 2) ? 1.f : 0.f);
    }
    #pragma unroll 1
    for (int i = tid; i < 2048; i += 256) {
        int o = i >> 4, l = i & 15;
        sBb[o * LDB0 + l] = g_bb[i];
    }

    const int wrow = (warp >> 2) * 32;   // 0 or 32
    const int wcol = (warp & 3) * 32;    // 0,32,64,96

    wmma::fragment<wmma::accumulator, 16, 16, 16, float> acc[2][2];
    #pragma unroll
    for (int m = 0; m < 2; m++)
        #pragma unroll
        for (int n = 0; n < 2; n++)
            wmma::fill_fragment(acc[m][n], 0.0f);

    #pragma unroll 1
    for (int c = 0; c < 2; c++) {
        __syncthreads();
        #pragma unroll 1
        for (int i = tid; i < 64 * 16; i += 256) {
            int row = i >> 4, q = i & 15;
            float4 v = make_float4(0.f, 0.f, 0.f, 0.f);
            if (r0 + row < N)
                v = *(const float4*)(x + (size_t)(r0 + row) * ROWLEN + 64 * c + 4 * q);
            __nv_bfloat16 h0 = __float2bfloat16(v.x), h1 = __float2bfloat16(v.y);
            __nv_bfloat16 h2 = __float2bfloat16(v.z), h3 = __float2bfloat16(v.w);
            float l0 = v.x - __bfloat162float(h0), l1 = v.y - __bfloat162float(h1);
            float l2 = v.z - __bfloat162float(h2), l3 = v.w - __bfloat162float(h3);
            __nv_bfloat162 hp0 = __halves2bfloat162(h0, h1);
            __nv_bfloat162 hp1 = __halves2bfloat162(h2, h3);
            __nv_bfloat162 lp0 = __floats2bfloat162_rn(l0, l1);
            __nv_bfloat162 lp1 = __floats2bfloat162_rn(l2, l3);
            uint2 uh; uh.x = *(uint32_t*)&hp0; uh.y = *(uint32_t*)&hp1;
            uint2 ul; ul.x = *(uint32_t*)&lp0; ul.y = *(uint32_t*)&lp1;
            *(uint2*)(sAh + row * LDA0 + 4 * q) = uh;
            *(uint2*)(sAl + row * LDA0 + 4 * q) = ul;
        }
        #pragma unroll 1
        for (int i = tid; i < 128 * 8; i += 256) {
            int o = i >> 3, q = i & 7;
            *(uint4*)(sWh + o * LDA0 + 8 * q) = *(const uint4*)(g_w0hi + o * 128 + 64 * c + 8 * q);
            *(uint4*)(sWl + o * LDA0 + 8 * q) = *(const uint4*)(g_w0lo + o * 128 + 64 * c + 8 * q);
        }
        __syncthreads();

        #pragma unroll
        for (int ks = 0; ks < 4; ks++) {
            wmma::fragment<wmma::matrix_b, 16, 16, 16, __nv_bfloat16, wmma::col_major> bh[2], bl[2];
            #pragma unroll
            for (int n = 0; n < 2; n++) {
                wmma::load_matrix_sync(bh[n], sWh + (wcol + 16 * n) * LDA0 + 16 * ks, LDA0);
                wmma::load_matrix_sync(bl[n], sWl + (wcol + 16 * n) * LDA0 + 16 * ks, LDA0);
            }
            #pragma unroll
            for (int m = 0; m < 2; m++) {
                wmma::fragment<wmma::matrix_a, 16, 16, 16, __nv_bfloat16, wmma::row_major> ah, al;
                wmma::load_matrix_sync(ah, sAh + (wrow + 16 * m) * LDA0 + 16 * ks, LDA0);
                wmma::load_matrix_sync(al, sAl + (wrow + 16 * m) * LDA0 + 16 * ks, LDA0);
                #pragma unroll
                for (int n = 0; n < 2; n++) {
                    wmma::mma_sync(acc[m][n], ah, bh[n], acc[m][n]);
                    wmma::mma_sync(acc[m][n], ah, bl[n], acc[m][n]);
                    wmma::mma_sync(acc[m][n], al, bh[n], acc[m][n]);
                }
            }
        }
    }

    {
        wmma::fragment<wmma::matrix_a, 16, 16, 16, __nv_bfloat16, wmma::row_major> aone;
        wmma::load_matrix_sync(aone, sOne, LDB0);
        #pragma unroll
        for (int n = 0; n < 2; n++) {
            wmma::fragment<wmma::matrix_b, 16, 16, 16, __nv_bfloat16, wmma::col_major> bb;
            wmma::load_matrix_sync(bb, sBb + (wcol + 16 * n) * LDB0, LDB0);
            #pragma unroll
            for (int m = 0; m < 2; m++)
                wmma::mma_sync(acc[m][n], aone, bb, acc[m][n]);
        }
    }

    #pragma unroll
    for (int m = 0; m < 2; m++)
        #pragma unroll
        for (int n = 0; n < 2; n++)
            #pragma unroll
            for (int e = 0; e < acc[m][n].num_elements; e++)
                acc[m][n].x[e] = act_fn(acc[m][n].x[e]);

    if (r0 + 64 <= N) {
        #pragma unroll
        for (int m = 0; m < 2; m++)
            #pragma unroll
            for (int n = 0; n < 2; n++)
                wmma::store_matrix_sync(out + (size_t)(r0 + wrow + 16 * m) * ROWLEN + wcol + 16 * n,
                                        acc[m][n], ROWLEN, wmma::mem_row_major);
    } else {
        __syncthreads();
        float* Os = smem;
        #pragma unroll
        for (int m = 0; m < 2; m++)
            #pragma unroll
            for (int n = 0; n < 2; n++)
                wmma::store_matrix_sync(Os + (wrow + 16 * m) * LDO0 + wcol + 16 * n,
                                        acc[m][n], LDO0, wmma::mem_row_major);
        __syncthreads();
        #pragma unroll 1
        for (int i = tid; i < 64 * 32; i += 256) {
            int row = i >> 5, q = i & 31;
            if (r0 + row < N) {
                const float* src = Os + row * LDO0 + 4 * q;
                float4 v; v.x = src[0]; v.y = src[1]; v.z = src[2]; v.w = src[3];
                *(float4*)(out + (size_t)(r0 + row) * ROWLEN + 4 * q) = v;
            }
        }
    }
}

// ===================== generic interleaved wmma kernel (seg1/seg2, unchanged) =====================
template<int MUL, int D, int R, int GPAD, int WGR, int WGC, int IN_OFF, int WOFF, int MINB>
__global__ __launch_bounds__(256, MINB)
void seg_wmma(const float* __restrict__ x, const float* __restrict__ bias,
              float* __restrict__ out, int N) {
    constexpr int K      = MUL;
    constexpr int GROWS  = R * D;
    constexpr int SEGLEN = MUL * D;
    constexpr int SEGF4  = SEGLEN / 4;
    constexpr int LDW    = K + 8;
    constexpr int LDO    = MUL + 4;
    constexpr int RT     = GPAD / 16;
    constexpr int CT     = MUL / 16;
    constexpr int WM     = RT / WGR;
    constexpr int WN     = CT / WGC;
    constexpr int KS     = K / 16;
    constexpr int ASZ    = GPAD * LDW / 2;
    constexpr int WSZ    = MUL * LDW / 2;
    constexpr int F_AH   = MUL;
    constexpr int F_AL   = F_AH + ASZ;
    constexpr int F_WH   = F_AL + ASZ;
    constexpr int F_WL   = F_WH + WSZ;
    static_assert(WGR * WGC == 8, "");
    static_assert(RT % WGR == 0 && CT % WGC == 0, "");
    static_assert(GPAD % 16 == 0 && GPAD >= GROWS, "");

    const int tid = threadIdx.x, warp = tid >> 5;
    const int r0 = blockIdx.x * R;
    const int nrows = min(R, N - r0);

    __nv_bfloat16* sAh = (__nv_bfloat16*)(smem + F_AH);
    __nv_bfloat16* sAl = (__nv_bfloat16*)(smem + F_AL);
    __nv_bfloat16* sWh = (__nv_bfloat16*)(smem + F_WH);
    __nv_bfloat16* sWl = (__nv_bfloat16*)(smem + F_WL);

    if (tid < MUL) smem[tid] = bias[tid];

    if (GPAD > GROWS) {
        constexpr int PADW = (GPAD - GROWS) * LDW / 2;
        uint32_t* ph = (uint32_t*)(sAh + GROWS * LDW);
        uint32_t* pl = (uint32_t*)(sAl + GROWS * LDW);
        #pragma unroll 1
        for (int i = tid; i < PADW; i += 256) { ph[i] = 0; pl[i] = 0; }
    }

    #pragma unroll 1
    for (int i = tid; i < R * SEGF4; i += 256) {
        int r = i / SEGF4, q = i - r * SEGF4;
        float4 v = make_float4(0.f, 0.f, 0.f, 0.f);
        if (r0 + r < N)
            v = *(const float4*)(x + (size_t)(r0 + r) * ROWLEN + IN_OFF + 4 * q);
        float vv[4] = {v.x, v.y, v.z, v.w};
        int j = 4 * q;
        #pragma unroll
        for (int e = 0; e < 4; e++) {
            int jj = j + e;
            int m  = jj / D;
            int d  = jj - m * D;
            float w = vv[e];
            __nv_bfloat16 h = __float2bfloat16(w);
            sAh[(r * D + d) * LDW + m] = h;
            sAl[(r * D + d) * LDW + m] = __float2bfloat16(w - __bfloat162float(h));
        }
    }
    #pragma unroll 1
    for (int i = tid; i < MUL * K / 8; i += 256) {
        int o = i / (K / 8), q = i - o * (K / 8);
        *(uint4*)(sWh + o * LDW + 8 * q) = *(const uint4*)(g_wshi + WOFF + o * K + 8 * q);
        *(uint4*)(sWl + o * LDW + 8 * q) = *(const uint4*)(g_wslo + WOFF + o * K + 8 * q);
    }
    __syncthreads();

    const int wr = (warp / WGC) * WM * 16;
    const int wc = (warp % WGC) * WN * 16;

    wmma::fragment<wmma::accumulator, 16, 16, 16, float> acc[WM][WN];
    #pragma unroll
    for (int m = 0; m < WM; m++)
        #pragma unroll
        for (int n = 0; n < WN; n++)
            wmma::fill_fragment(acc[m][n], 0.0f);

    #pragma unroll
    for (int ks = 0; ks < KS; ks++) {
        wmma::fragment<wmma::matrix_b, 16, 16, 16, __nv_bfloat16, wmma::col_major> bh[WN], bl[WN];
        #pragma unroll
        for (int n = 0; n < WN; n++) {
            wmma::load_matrix_sync(bh[n], sWh + (wc + 16 * n) * LDW + 16 * ks, LDW);
            wmma::load_matrix_sync(bl[n], sWl + (wc + 16 * n) * LDW + 16 * ks, LDW);
        }
        #pragma unroll
        for (int m = 0; m < WM; m++) {
            wmma::fragment<wmma::matrix_a, 16, 16, 16, __nv_bfloat16, wmma::row_major> ah, al;
            wmma::load_matrix_sync(ah, sAh + (wr + 16 * m) * LDW + 16 * ks, LDW);
            wmma::load_matrix_sync(al, sAl + (wr + 16 * m) * LDW + 16 * ks, LDW);
            #pragma unroll
            for (int n = 0; n < WN; n++) {
                wmma::mma_sync(acc[m][n], ah, bh[n], acc[m][n]);
                wmma::mma_sync(acc[m][n], ah, bl[n], acc[m][n]);
                wmma::mma_sync(acc[m][n], al, bh[n], acc[m][n]);
            }
        }
    }
    __syncthreads();

    float* Os = smem + F_AH;
    #pragma unroll
    for (int m = 0; m < WM; m++)
        #pragma unroll
        for (int n = 0; n < WN; n++)
            wmma::store_matrix_sync(Os + (wr + 16 * m) * LDO + wc + 16 * n,
                                    acc[m][n], LDO, wmma::mem_row_major);
    __syncthreads();

    const float* bias_s = smem;
    #pragma unroll 1
    for (int i = tid; i < nrows * SEGF4; i += 256) {
        int r = i / SEGF4, q = i - r * SEGF4;
        int j = 4 * q;
        float vv[4];
        #pragma unroll
        for (int e = 0; e < 4; e++) {
            int jj = j + e;
            int o  = jj / D;
            int d  = jj - o * D;
            vv[e] = Os[(r * D + d) * LDO + o] + bias_s[o];
        }
        float4 v; v.x = vv[0]; v.y = vv[1]; v.z = vv[2]; v.w = vv[3];
        *(float4*)(out + (size_t)(r0 + r) * ROWLEN + IN_OFF + 4 * q) = v;
    }
}

// ===================== seg3: FFMA2 (unchanged) =====================
template<int MUL, int D, int R, int NW, int CW, int TO, int KPH,
         int IN_OFF, int WOFF, bool ACT, int MINB>
__global__ __launch_bounds__(NW * 32, MINB)
void seg_s0(const float* __restrict__ x, const float* __restrict__ bias,
            float* __restrict__ out, int N) {
    constexpr int NT     = NW * 32;
    constexpr int K      = MUL;
    constexpr int KCH    = K / KPH;
    constexpr int SEGLEN = MUL * D;
    constexpr int SEGF4  = SEGLEN / 4;
    constexpr int CBLK   = R * D;
    constexpr int OW     = NW / CW;
    constexpr int CPW    = CBLK / CW;
    constexpr int TC     = CPW / 32;
    constexpr int TOH    = TO / 2;
    constexpr int TOQ    = TO / 4;
    constexpr int P      = SEGLEN + ((32 + D - (SEGLEN % 32)) % 32);

    float* Ws = smem;
    float* Xs = smem + KCH * MUL;
    float* Os = Xs;

    const int tid = threadIdx.x, lane = tid & 31, warp = tid >> 5;
    const int r0 = blockIdx.x * R;
    const int nrows = min(R, N - r0);
    const int ob = (warp % OW) * TO;
    const int cbase = (warp / OW) * CPW + lane;

    const int nld = nrows * SEGF4;
    #pragma unroll 1
    for (int i = tid; i < nld; i += NT) {
        int r = i / SEGF4, q = i - r * SEGF4;
        float4 v = *(const float4*)(x + (size_t)(r0 + r) * ROWLEN + IN_OFF + 4 * q);
        float* dst = Xs + r * P + 4 * q;
        dst[0] = v.x; dst[1] = v.y; dst[2] = v.z; dst[3] = v.w;
    }

    int bx[TC];
    #pragma unroll
    for (int i = 0; i < TC; i++) {
        int c = cbase + 32 * i;
        bx[i] = (c / D) * P + (c % D);
    }

    u64 acc[TC][TOH];
    #pragma unroll
    for (int p = 0; p < TOH; p++) {
        u64 bp = pack2(__ldg(bias + ob + 2 * p), __ldg(bias + ob + 2 * p + 1));
        #pragma unroll
        for (int i = 0; i < TC; i++) acc[i][p] = bp;
    }

    #pragma unroll
    for (int ph = 0; ph < KPH; ph++) {
        if (ph) __syncthreads();
        #pragma unroll 1
        for (int i = tid; i < KCH * MUL / 4; i += NT)
            ((float4*)Ws)[i] = ((const float4*)(g_wt + WOFF + ph * KCH * MUL))[i];
        __syncthreads();

        #pragma unroll 8
        for (int kl = 0; kl < KCH; kl++) {
            int k = ph * KCH + kl;
            u64 xd[TC];
            #pragma unroll
            for (int i = 0; i < TC; i++) {
                float xv = Xs[bx[i] + k * D];
                xd[i] = pack2(xv, xv);
            }
            const ulonglong2* wq = (const ulonglong2*)(Ws + kl * MUL + ob);
            #pragma unroll
            for (int j = 0; j < TOQ; j++) {
                ulonglong2 w2 = wq[j];
                #pragma unroll
                for (int i = 0; i < TC; i++) {
                    acc[i][2 * j]     = ffma2(xd[i], w2.x, acc[i][2 * j]);
                    acc[i][2 * j + 1] = ffma2(xd[i], w2.y, acc[i][2 * j + 1]);
                }
            }
        }
    }
    __syncthreads();

    #pragma unroll
    for (int i = 0; i < TC; i++) {
        int c = cbase + 32 * i;
        float* od = Os + (c / D) * P + (c % D);
        #pragma unroll
        for (int p = 0; p < TOH; p++) {
            float lo, hi; unpack2(acc[i][p], lo, hi);
            od[(ob + 2 * p) * D]     = lo;
            od[(ob + 2 * p + 1) * D] = hi;
        }
    }
    __syncthreads();

    #pragma unroll 1
    for (int i = tid; i < nld; i += NT) {
        int r = i / SEGF4, q = i - r * SEGF4;
        const float* src = Os + r * P + 4 * q;
        float4 v;
        v.x = src[0]; v.y = src[1]; v.z = src[2]; v.w = src[3];
        *(float4*)(out + (size_t)(r0 + r) * ROWLEN + IN_OFF + 4 * q) = v;
    }
}

constexpr int pitch_of(int seglen, int d) {
    return seglen + ((32 + d - (seglen % 32)) % 32);
}

// ---- streams/events: fork at entry, each stream runs its own prep + seg ----
static cudaStream_t g_side[3];
static cudaEvent_t  g_ev_root;
static cudaEvent_t  g_ev_done[3];
static bool         g_init_done = false;

extern "C" void kernel_launch(void* const* d_in, const int* in_sizes, int n_in,
                              void* d_out, int out_size) {
    const float* x  = (const float*)d_in[0];
    const float* w0 = (const float*)d_in[1];
    const float* w1 = (const float*)d_in[2];
    const float* w2 = (const float*)d_in[3];
    const float* w3 = (const float*)d_in[4];
    const float* b0 = (const float*)d_in[5];
    const float* b1 = (const float*)d_in[6];
    const float* b2 = (const float*)d_in[7];
    const float* b3 = (const float*)d_in[8];
    float* out = (float*)d_out;
    const int N = in_sizes[0] / ROWLEN;

    if (!g_init_done) {
        for (int i = 0; i < 3; i++)
            cudaStreamCreateWithFlags(&g_side[i], cudaStreamNonBlocking);
        cudaEventCreateWithFlags(&g_ev_root, cudaEventDisableTiming);
        for (int i = 0; i < 3; i++)
            cudaEventCreateWithFlags(&g_ev_done[i], cudaEventDisableTiming);
        g_init_done = true;
    }

    // seg1: MUL=64, D=3, R=32 -> GROWS=96=GPAD: RT=6; warps 2x4 -> WM=3, WN=1
    auto k1 = seg_wmma<64, 3, 32,  96, 2, 4, 128,    0, 4>;
    // seg2: MUL=32, D=5, R=32 -> GROWS=160, GPAD=192: RT=12; warps 4x2 -> WM=3, WN=1
    auto k2 = seg_wmma<32, 5, 32, 192, 4, 2, 320, 4096, 4>;
    // seg3: FFMA2
    auto k3 = seg_s0< 16, 7, 32, 4, 1, 4, 1, 480, 21504, false, 8>;

    constexpr int SM1 = (64 + 2 * (96 * 72 / 2)  + 2 * (64 * 72 / 2)) * 4;   // 46336
    constexpr int SM2 = (32 + 2 * (192 * 40 / 2) + 2 * (32 * 40 / 2)) * 4;   // 35968
    constexpr int S3  = (16 * 16 + 32 * pitch_of(112, 7)) * 4;               // 18304

    cudaFuncSetAttribute(seg0_wmma, cudaFuncAttributeMaxDynamicSharedMemorySize, SM0_BYTES);
    cudaFuncSetAttribute(k1, cudaFuncAttributeMaxDynamicSharedMemorySize, SM1);
    cudaFuncSetAttribute(k2, cudaFuncAttributeMaxDynamicSharedMemorySize, SM2);
    cudaFuncSetAttribute(k3, cudaFuncAttributeMaxDynamicSharedMemorySize, S3);

    const int g64 = (N + 63) / 64;   // 1563
    const int g32 = (N + 31) / 32;   // 3125

    // ---- fork FIRST: each stream owns its (prep -> seg) chain ----
    cudaEventRecord(g_ev_root, 0);
    for (int i = 0; i < 3; i++)
        cudaStreamWaitEvent(g_side[i], g_ev_root, 0);

    // main: W0+bias prep, then seg0
    prep_main<<<72, 256>>>(w0, b0);
    seg0_wmma<<<g64, 256, SM0_BYTES>>>(x, out, N);

    // side0: W1 prep, then seg1
    prep_s1<<<16, 256, 0, g_side[0]>>>(w1);
    k1<<<g32, 256, SM1, g_side[0]>>>(x, b1, out, N);

    // side1: W2 prep, then seg2
    prep_s2<<<4, 256, 0, g_side[1]>>>(w2);
    k2<<<g32, 256, SM2, g_side[1]>>>(x, b2, out, N);

    // side2: W3 prep, then seg3
    prep_s3<<<1, 256, 0, g_side[2]>>>(w3);
    k3<<<g32, 128, S3, g_side[2]>>>(x, b3, out, N);

    // ---- join back onto the main (capture) stream ----
    for (int i = 0; i < 3; i++) {
        cudaEventRecord(g_ev_done[i], g_side[i]);
        cudaStreamWaitEvent(0, g_ev_done[i], 0);
    }
}